// round 2
// baseline (speedup 1.0000x reference)
#include <cuda_runtime.h>

#define HID 50
#define GP  224      // gates padded: 4 gates * 56 j-slots (j<50 real)
#define K4N 13       // k padded 50->52, 4 per float4
#define BT  16       // batch rows per CTA
#define NTHREADS 256
#define GSTRIDE 225  // gates_s row stride (floats), odd -> conflict-free update reads
#define HLSTRIDE 53

typedef unsigned long long u64;

// Packed fp32x2 FMA (Blackwell): 2 fp32 FMAs per instruction, exact fp32.
__device__ __forceinline__ void ffma2(u64& d, u64 a, u64 b) {
    asm("fma.rn.f32x2 %0, %1, %2, %3;" : "=l"(d) : "l"(a), "l"(b), "l"(d));
}

__device__ __forceinline__ float sigmoidf_(float x) {
    float e = __expf(-x);
    return __fdividef(1.f, 1.f + e);
}
__device__ __forceinline__ float tanhf_(float x) {
    float e = __expf(2.f * x);
    return 1.f - __fdividef(2.f, e + 1.f);
}

__global__ void __launch_bounds__(NTHREADS, 1)
seq2seq_kernel(const float* __restrict__ source,
               const float* __restrict__ eWih, const float* __restrict__ eWhh,
               const float* __restrict__ eBih, const float* __restrict__ eBhh,
               const float* __restrict__ dWih, const float* __restrict__ dWhh,
               const float* __restrict__ dBih, const float* __restrict__ dBhh,
               const float* __restrict__ fcW,  const float* __restrict__ fcB,
               float* __restrict__ out, int S, int T)
{
    extern __shared__ char smem_raw[];
    float4* wenc  = (float4*)smem_raw;          // [K4N][GP] w[g][4k4..4k4+3]
    float4* wdec  = wenc + K4N * GP;
    float4* hpk   = wdec + K4N * GP;            // [K4N][BT] h[b][4k4..4k4+3]
    float*  gates = (float*)(hpk + K4N * BT);   // [BT][GSTRIDE]
    float*  hlin  = gates + BT * GSTRIDE;       // [BT][HLSTRIDE]
    float*  xdec  = hlin + BT * HLSTRIDE;       // [BT]
    float*  fcw   = xdec + BT;                  // [HID]
    float*  fcb   = fcw + HID;                  // [2]
    float*  srcs  = fcb + 2;                    // [BT][S]

    const int tid   = threadIdx.x;
    const int lane  = tid & 31;
    const int wrp   = tid >> 5;
    const int b0    = blockIdx.x * BT;

    // ---- GEMM tile assignment: 2 batch x 7 gates per thread.
    // warp w owns gate-groups {4w..4w+3}; lane = bgrp*4 + (gg & 3)
    const int bgrp  = lane >> 2;            // [0,8): batch pair index
    const int ggl   = lane & 3;             // gate-group within warp
    const int gg    = wrp * 4 + ggl;        // [0,32)
    const int gbase = gg * 7;               // [0,224)
    const int br    = bgrp * 2;             // first batch row of pair

    // ---- build packed (transposed, padded) weight tiles, both phases at once
    for (int idx = tid; idx < K4N * GP; idx += NTHREADS) {
        int k4 = idx / GP, g = idx % GP;
        int gate = g / 56, j = g % 56;
        float4 ve = make_float4(0.f, 0.f, 0.f, 0.f), vd = ve;
        if (j < HID) {
            int row = gate * HID + j;
            #pragma unroll
            for (int c = 0; c < 4; c++) {
                int k = 4 * k4 + c;
                if (k < HID) {
                    ((float*)&ve)[c] = eWhh[row * HID + k];
                    ((float*)&vd)[c] = dWhh[row * HID + k];
                }
            }
        }
        wenc[idx] = ve;
        wdec[idx] = vd;
    }
    for (int i = tid; i < K4N * BT; i += NTHREADS) hpk[i] = make_float4(0.f, 0.f, 0.f, 0.f);
    if (tid < BT)  xdec[tid] = 0.f;
    if (tid < HID) fcw[tid] = fcW[tid];
    if (tid == 0)  fcb[0] = fcB[0];
    for (int bl = 0; bl < BT; bl++)
        for (int t = tid; t < S; t += NTHREADS)
            srcs[bl * S + t] = source[(size_t)(b0 + bl) * S + t];

    // ---- per-thread persistent state
    float biasr[7], wihr[7];                 // per-gate constants (shared by both b rows)
    const int bu = tid & 15;                 // update role: batch row
    const int j0 = tid >> 4;                 // update role: base hidden index
    float c0 = 0.f, c1 = 0.f, c2 = 0.f, c3 = 0.f;

    #pragma unroll
    for (int i = 0; i < 7; i++) {
        int g = gbase + i, gate = g / 56, j = g % 56;
        if (j < HID) { int r = gate * HID + j; biasr[i] = eBih[r] + eBhh[r]; wihr[i] = eWih[r]; }
        else         { biasr[i] = 0.f; wihr[i] = 0.f; }
    }
    __syncthreads();

    // GEMM: gates[br+p][gbase+i] = bias + x_p*wih + sum_k h*w, f32x2 along k
    auto gemm = [&](const float4* wp, float x0v, float x1v) {
        u64 acc0[7], acc1[7];
        #pragma unroll
        for (int i = 0; i < 7; i++) {
            acc0[i] = (u64)__float_as_uint(fmaf(x0v, wihr[i], biasr[i]));
            acc1[i] = (u64)__float_as_uint(fmaf(x1v, wihr[i], biasr[i]));
        }
        const ulonglong2* hp2 = (const ulonglong2*)hpk;
        const ulonglong2* wp2 = (const ulonglong2*)wp;
        #pragma unroll
        for (int k4 = 0; k4 < K4N; k4++) {
            ulonglong2 hv0 = hp2[k4 * BT + br];       // 8 addrs/warp: 1 wavefront
            ulonglong2 hv1 = hp2[k4 * BT + br + 1];
            #pragma unroll
            for (int i = 0; i < 7; i++) {
                ulonglong2 wv = wp2[k4 * GP + gbase + i];  // 4 addrs/warp: broadcast
                ffma2(acc0[i], wv.x, hv0.x);
                ffma2(acc0[i], wv.y, hv0.y);
                ffma2(acc1[i], wv.x, hv1.x);
                ffma2(acc1[i], wv.y, hv1.y);
            }
        }
        #pragma unroll
        for (int i = 0; i < 7; i++) {
            u64 a0 = acc0[i], a1 = acc1[i];
            gates[br * GSTRIDE + gbase + i] =
                __uint_as_float((unsigned)a0) + __uint_as_float((unsigned)(a0 >> 32));
            gates[(br + 1) * GSTRIDE + gbase + i] =
                __uint_as_float((unsigned)a1) + __uint_as_float((unsigned)(a1 >> 32));
        }
    };

    auto upd_one = [&](int j, float& c) {
        float gi = gates[bu * GSTRIDE + j];
        float gf = gates[bu * GSTRIDE + 56 + j];
        float gg_ = gates[bu * GSTRIDE + 112 + j];
        float go = gates[bu * GSTRIDE + 168 + j];
        float iv = sigmoidf_(gi);
        float fv = sigmoidf_(gf);
        float gv = tanhf_(gg_);
        float ov = sigmoidf_(go);
        c = fmaf(fv, c, iv * gv);
        float h = ov * tanhf_(c);
        ((float*)hpk)[(j >> 2) * (BT * 4) + bu * 4 + (j & 3)] = h;
        hlin[bu * HLSTRIDE + j] = h;
    };

    auto update = [&]() {
        upd_one(j0,      c0);
        upd_one(j0 + 16, c1);
        upd_one(j0 + 32, c2);
        if (j0 < 2) upd_one(j0 + 48, c3);   // j = 48,49
    };

    // ================= encoder =================
    for (int t = 0; t < S; t++) {
        float x0v = srcs[br * S + t];
        float x1v = srcs[(br + 1) * S + t];
        gemm(wenc, x0v, x1v);
        __syncthreads();
        update();
        __syncthreads();
    }

    // ================= decoder =================
    #pragma unroll
    for (int i = 0; i < 7; i++) {
        int g = gbase + i, gate = g / 56, j = g % 56;
        if (j < HID) { int r = gate * HID + j; biasr[i] = dBih[r] + dBhh[r]; wihr[i] = dWih[r]; }
        else         { biasr[i] = 0.f; wihr[i] = 0.f; }
    }
    for (int t = 0; t < T; t++) {
        float x0v = xdec[br];
        float x1v = xdec[br + 1];
        gemm(wdec, x0v, x1v);
        __syncthreads();
        update();
        __syncthreads();
        if (wrp == 0) {  // fc: y[b] = h . fcW + fcb, 2 lanes per batch row
            const int bfc = lane & 15;
            const int hhf = lane >> 4;
            float s = 0.f;
            #pragma unroll
            for (int jj = 0; jj < 25; jj++) {
                int j = hhf * 25 + jj;
                s = fmaf(hlin[bfc * HLSTRIDE + j], fcw[j], s);
            }
            s += __shfl_xor_sync(0xffffffffu, s, 16);
            if (hhf == 0) {
                float y = s + fcb[0];
                xdec[bfc] = y;
                out[(size_t)(b0 + bfc) * T + t] = y;
            }
        }
        __syncthreads();
    }
}

extern "C" void kernel_launch(void* const* d_in, const int* in_sizes, int n_in,
                              void* d_out, int out_size)
{
    const float* source = (const float*)d_in[0];
    const float* eWih = (const float*)d_in[1];
    const float* eWhh = (const float*)d_in[2];
    const float* eBih = (const float*)d_in[3];
    const float* eBhh = (const float*)d_in[4];
    const float* dWih = (const float*)d_in[5];
    const float* dWhh = (const float*)d_in[6];
    const float* dBih = (const float*)d_in[7];
    const float* dBhh = (const float*)d_in[8];
    const float* fcW  = (const float*)d_in[9];
    const float* fcB  = (const float*)d_in[10];
    float* out = (float*)d_out;

    const int B = 2048;
    const int S = in_sizes[0] / B;   // 512
    const int T = out_size   / B;    // 256

    size_t sm = sizeof(float4) * (size_t)K4N * GP * 2
              + sizeof(float4) * (size_t)K4N * BT
              + sizeof(float)  * (size_t)(BT * GSTRIDE + BT * HLSTRIDE + BT + HID + 2)
              + sizeof(float)  * (size_t)BT * S;

    cudaFuncSetAttribute(seq2seq_kernel, cudaFuncAttributeMaxDynamicSharedMemorySize, (int)sm);
    seq2seq_kernel<<<B / BT, NTHREADS, sm>>>(source, eWih, eWhh, eBih, eBhh,
                                             dWih, dWhh, dBih, dBhh, fcW, fcB,
                                             out, S, T);
}

// round 3
// speedup vs baseline: 1.0545x; 1.0545x over previous
#include <cuda_runtime.h>

#define HID 50
#define GP  224      // gates padded: 4 gates * 56 j-slots (j<50 real)
#define K4N 13       // k padded 50->52, 4 per float4
#define BT  16       // batch rows per CTA
#define NTHREADS 512
#define GSTRIDE 225  // gates_s row stride (floats)
#define HLSTRIDE 53

typedef unsigned long long u64;

// Packed fp32x2 FMA (Blackwell): 2 fp32 FMAs per instruction, exact fp32.
__device__ __forceinline__ void ffma2(u64& d, u64 a, u64 b) {
    asm("fma.rn.f32x2 %0, %1, %2, %3;" : "=l"(d) : "l"(a), "l"(b), "l"(d));
}

__device__ __forceinline__ float sigmoidf_(float x) {
    float e = __expf(-x);
    return __fdividef(1.f, 1.f + e);
}
__device__ __forceinline__ float tanhf_(float x) {
    float e = __expf(2.f * x);
    return 1.f - __fdividef(2.f, e + 1.f);
}

__global__ void __launch_bounds__(NTHREADS, 1)
seq2seq_kernel(const float* __restrict__ source,
               const float* __restrict__ eWih, const float* __restrict__ eWhh,
               const float* __restrict__ eBih, const float* __restrict__ eBhh,
               const float* __restrict__ dWih, const float* __restrict__ dWhh,
               const float* __restrict__ dBih, const float* __restrict__ dBhh,
               const float* __restrict__ fcW,  const float* __restrict__ fcB,
               float* __restrict__ out, int S, int T)
{
    extern __shared__ char smem_raw[];
    float4* wenc  = (float4*)smem_raw;          // [K4N][GP] w[g][4k4..4k4+3]
    float4* wdec  = wenc + K4N * GP;
    float4* hpk   = wdec + K4N * GP;            // [K4N][BT] h[b][4k4..4k4+3]
    float*  gates = (float*)(hpk + K4N * BT);   // [BT][GSTRIDE]
    float*  hlin  = gates + BT * GSTRIDE;       // [BT][HLSTRIDE]
    float*  xdec  = hlin + BT * HLSTRIDE;       // [BT]
    float*  fcw   = xdec + BT;                  // [HID]
    float*  fcb   = fcw + HID;                  // [2]
    float*  srcs  = fcb + 2;                    // [BT][S]

    const int tid   = threadIdx.x;
    const int lane  = tid & 31;
    const int wrp   = tid >> 5;                 // [0,16)
    const int b0    = blockIdx.x * BT;

    // ---- GEMM tile: 1 batch x 7 gates per thread.
    // warp w owns gate-groups {2w, 2w+1}; lane = bgrp*2 + ggl
    const int bgrp  = lane >> 1;                // [0,16): batch row
    const int ggl   = lane & 1;                 // gate-group parity within warp
    const int gg    = wrp * 2 + ggl;            // [0,32)
    const int gbase = gg * 7;                   // [0,224)

    // ---- build packed (transposed, padded) weight tiles, both phases at once
    for (int idx = tid; idx < K4N * GP; idx += NTHREADS) {
        int k4 = idx / GP, g = idx % GP;
        int gate = g / 56, j = g % 56;
        float4 ve = make_float4(0.f, 0.f, 0.f, 0.f), vd = ve;
        if (j < HID) {
            int row = gate * HID + j;
            #pragma unroll
            for (int c = 0; c < 4; c++) {
                int k = 4 * k4 + c;
                if (k < HID) {
                    ((float*)&ve)[c] = eWhh[row * HID + k];
                    ((float*)&vd)[c] = dWhh[row * HID + k];
                }
            }
        }
        wenc[idx] = ve;
        wdec[idx] = vd;
    }
    for (int i = tid; i < K4N * BT; i += NTHREADS) hpk[i] = make_float4(0.f, 0.f, 0.f, 0.f);
    if (tid < BT)  xdec[tid] = 0.f;
    if (tid < HID) fcw[tid] = fcW[tid];
    if (tid == 0)  fcb[0] = fcB[0];
    for (int bl = 0; bl < BT; bl++)
        for (int t = tid; t < S; t += NTHREADS)
            srcs[bl * S + t] = source[(size_t)(b0 + bl) * S + t];

    // ---- per-thread persistent state
    float biasr[7], wihr[7];                    // per-gate constants
    // update role: cell idx = tid (always) and tid+512 (if < 800); b = idx&15, j = idx>>4
    const int bu0 = tid & 15,        ju0 = tid >> 4;          // ju0 in [0,32)
    const int bu1 = (tid + 512) & 15, ju1 = (tid + 512) >> 4; // ju1 in [32,50) when valid
    const bool has1 = (tid + 512) < BT * HID;                 // tid < 288
    float c0 = 0.f, c1 = 0.f;

    #pragma unroll
    for (int i = 0; i < 7; i++) {
        int g = gbase + i, gate = g / 56, j = g % 56;
        if (j < HID) { int r = gate * HID + j; biasr[i] = eBih[r] + eBhh[r]; wihr[i] = eWih[r]; }
        else         { biasr[i] = 0.f; wihr[i] = 0.f; }
    }
    __syncthreads();

    // GEMM: gates[bgrp][gbase+i] = bias + x*wih + sum_k h*w, f32x2 along k
    auto gemm = [&](const float4* wp, float xv) {
        u64 acc[7];
        #pragma unroll
        for (int i = 0; i < 7; i++)
            acc[i] = (u64)__float_as_uint(fmaf(xv, wihr[i], biasr[i]));
        const ulonglong2* hp2 = (const ulonglong2*)hpk;
        const ulonglong2* wp2 = (const ulonglong2*)wp;
        #pragma unroll
        for (int k4 = 0; k4 < K4N; k4++) {
            ulonglong2 hv = hp2[k4 * BT + bgrp];          // 16 distinct 16B: 2 wavefronts
            #pragma unroll
            for (int i = 0; i < 7; i++) {
                ulonglong2 wv = wp2[k4 * GP + gbase + i]; // 2 distinct 16B: broadcast
                ffma2(acc[i], wv.x, hv.x);
                ffma2(acc[i], wv.y, hv.y);
            }
        }
        #pragma unroll
        for (int i = 0; i < 7; i++) {
            u64 a = acc[i];
            gates[bgrp * GSTRIDE + gbase + i] =
                __uint_as_float((unsigned)a) + __uint_as_float((unsigned)(a >> 32));
        }
    };

    auto upd_one = [&](int b, int j, float& c) {
        float gi  = gates[b * GSTRIDE + j];
        float gf  = gates[b * GSTRIDE + 56 + j];
        float gg_ = gates[b * GSTRIDE + 112 + j];
        float go  = gates[b * GSTRIDE + 168 + j];
        float iv = sigmoidf_(gi);
        float fv = sigmoidf_(gf);
        float gv = tanhf_(gg_);
        float ov = sigmoidf_(go);
        c = fmaf(fv, c, iv * gv);
        float h = ov * tanhf_(c);
        ((float*)hpk)[(j >> 2) * (BT * 4) + b * 4 + (j & 3)] = h;
        hlin[b * HLSTRIDE + j] = h;
    };

    auto update = [&]() {
        upd_one(bu0, ju0, c0);
        if (has1) upd_one(bu1, ju1, c1);
    };

    // ================= encoder =================
    for (int t = 0; t < S; t++) {
        float xv = srcs[bgrp * S + t];
        gemm(wenc, xv);
        __syncthreads();
        update();
        __syncthreads();
    }

    // ================= decoder =================
    #pragma unroll
    for (int i = 0; i < 7; i++) {
        int g = gbase + i, gate = g / 56, j = g % 56;
        if (j < HID) { int r = gate * HID + j; biasr[i] = dBih[r] + dBhh[r]; wihr[i] = dWih[r]; }
        else         { biasr[i] = 0.f; wihr[i] = 0.f; }
    }
    for (int t = 0; t < T; t++) {
        float xv = xdec[bgrp];
        gemm(wdec, xv);
        __syncthreads();
        update();
        __syncthreads();
        if (wrp == 0) {  // fc: y[b] = h . fcW + fcb, 2 lanes per batch row
            const int bfc = lane & 15;
            const int hhf = lane >> 4;
            float s = 0.f;
            #pragma unroll
            for (int jj = 0; jj < 25; jj++) {
                int j = hhf * 25 + jj;
                s = fmaf(hlin[bfc * HLSTRIDE + j], fcw[j], s);
            }
            s += __shfl_xor_sync(0xffffffffu, s, 16);
            if (hhf == 0) {
                float y = s + fcb[0];
                xdec[bfc] = y;
                out[(size_t)(b0 + bfc) * T + t] = y;
            }
        }
        __syncthreads();
    }
}

extern "C" void kernel_launch(void* const* d_in, const int* in_sizes, int n_in,
                              void* d_out, int out_size)
{
    const float* source = (const float*)d_in[0];
    const float* eWih = (const float*)d_in[1];
    const float* eWhh = (const float*)d_in[2];
    const float* eBih = (const float*)d_in[3];
    const float* eBhh = (const float*)d_in[4];
    const float* dWih = (const float*)d_in[5];
    const float* dWhh = (const float*)d_in[6];
    const float* dBih = (const float*)d_in[7];
    const float* dBhh = (const float*)d_in[8];
    const float* fcW  = (const float*)d_in[9];
    const float* fcB  = (const float*)d_in[10];
    float* out = (float*)d_out;

    const int B = 2048;
    const int S = in_sizes[0] / B;   // 512
    const int T = out_size   / B;    // 256

    size_t sm = sizeof(float4) * (size_t)K4N * GP * 2
              + sizeof(float4) * (size_t)K4N * BT
              + sizeof(float)  * (size_t)(BT * GSTRIDE + BT * HLSTRIDE + BT + HID + 2)
              + sizeof(float)  * (size_t)BT * S;

    cudaFuncSetAttribute(seq2seq_kernel, cudaFuncAttributeMaxDynamicSharedMemorySize, (int)sm);
    seq2seq_kernel<<<B / BT, NTHREADS, sm>>>(source, eWih, eWhh, eBih, eBhh,
                                             dWih, dWhh, dBih, dBhh, fcW, fcB,
                                             out, S, T);
}